// round 2
// baseline (speedup 1.0000x reference)
#include <cuda_runtime.h>
#include <cuda_bf16.h>

#define N_NODES  100000
#define N_EDGES  1600000
#define N_GRAPHS 1000

// ---------------- scratch (static __device__, no allocs) ----------------
__device__ float g_deg[N_NODES];
__device__ float g_dinv[N_NODES];
__device__ float g_nw[N_EDGES];
__device__ float g_m[N_NODES * 64];    // layer0 dense transform
__device__ float g_h[N_NODES * 64];    // layer0 agg -> h (in place)
__device__ float g_m2[N_NODES * 32];   // layer1 dense transform
__device__ float g_h2[N_NODES * 32];   // layer1 agg -> h2 (in place)
__device__ float g_pool[N_GRAPHS * 32];

// ---------------- degree ----------------
__global__ void deg_kernel(const int* __restrict__ dst, const float* __restrict__ w, int E) {
    int e = blockIdx.x * blockDim.x + threadIdx.x;
    if (e < E) atomicAdd(&g_deg[dst[e]], w[e]);
}

__global__ void dinv_kernel(int n) {
    int i = blockIdx.x * blockDim.x + threadIdx.x;
    if (i < n) {
        float d = g_deg[i] + 1.0f;  // self loop weight 1
        g_dinv[i] = rsqrtf(fmaxf(d, 1e-12f));
    }
}

__global__ void nw_kernel(const int* __restrict__ src, const int* __restrict__ dst,
                          const float* __restrict__ w, int E) {
    int e = blockIdx.x * blockDim.x + threadIdx.x;
    if (e < E) g_nw[e] = g_dinv[src[e]] * w[e] * g_dinv[dst[e]];
}

// ---------------- tiled GEMM: out[N,M] = X[N,K] @ W[K,M] ----------------
// 32 rows per block, 256 threads, each thread: 2 rows x (M/16) cols.
template <int K, int M>
__global__ void gemm_kernel(const float* __restrict__ X, const float* __restrict__ W,
                            float* __restrict__ out, int nrows) {
    __shared__ float Ws[K * M];
    __shared__ float Xs[32 * K];

    for (int i = threadIdx.x; i < K * M; i += 256) Ws[i] = W[i];
    int row0 = blockIdx.x * 32;
    int nr = nrows - row0; if (nr > 32) nr = 32;
    for (int i = threadIdx.x; i < nr * K; i += 256) Xs[i] = X[row0 * K + i];
    __syncthreads();

    constexpr int CPT = M / 16;              // 4 for M=64, 2 for M=32
    int tx = threadIdx.x & 15;               // col group
    int ty = threadIdx.x >> 4;               // row group (16 groups x 2 rows)

    float acc[2][CPT];
#pragma unroll
    for (int r = 0; r < 2; r++)
#pragma unroll
        for (int c = 0; c < CPT; c++) acc[r][c] = 0.f;

#pragma unroll 4
    for (int k = 0; k < K; k++) {
        float x0 = Xs[(ty * 2 + 0) * K + k];
        float x1 = Xs[(ty * 2 + 1) * K + k];
        if (CPT == 4) {
            float4 w4 = *reinterpret_cast<const float4*>(&Ws[k * M + tx * 4]);
            acc[0][0] += x0 * w4.x; acc[0][1] += x0 * w4.y;
            acc[0][2] += x0 * w4.z; acc[0][3] += x0 * w4.w;
            acc[1][0] += x1 * w4.x; acc[1][1] += x1 * w4.y;
            acc[1][2] += x1 * w4.z; acc[1][3] += x1 * w4.w;
        } else {
            float2 w2 = *reinterpret_cast<const float2*>(&Ws[k * M + tx * 2]);
            acc[0][0] += x0 * w2.x; acc[0][1] += x0 * w2.y;
            acc[1][0] += x1 * w2.x; acc[1][1] += x1 * w2.y;
        }
    }

#pragma unroll
    for (int r = 0; r < 2; r++) {
        int row = row0 + ty * 2 + r;
        if (row < nrows) {
#pragma unroll
            for (int c = 0; c < CPT; c++) out[row * M + tx * CPT + c] = acc[r][c];
        }
    }
}

// ---------------- edge aggregation: agg[dst] += m[src] * nw ----------------
// One float2 payload element per thread. LOG = log2(F/2): 5 for F=64, 4 for F=32.
template <int LOG>
__global__ void edge_agg_kernel(const int* __restrict__ src, const int* __restrict__ dst,
                                const float* __restrict__ m, float* __restrict__ agg) {
    const int PER = 1 << LOG;
    int id = blockIdx.x * blockDim.x + threadIdx.x;
    int e = id >> LOG;
    if (e >= N_EDGES) return;
    int f = id & (PER - 1);
    int s = src[e];
    int d = dst[e];
    float w = g_nw[e];
    float2 v = reinterpret_cast<const float2*>(m)[s * PER + f];
    float* a = agg + ((d << LOG) + f) * 2;
    atomicAdd(a + 0, v.x * w);
    atomicAdd(a + 1, v.y * w);
}

// ---------------- finalize: h = relu(agg + m*dinv^2 + b), in place on agg ----------------
template <int LOGF>
__global__ void finalize_kernel(const float* __restrict__ m, float* __restrict__ agg,
                                const float* __restrict__ b) {
    const int F = 1 << LOGF;
    int id = blockIdx.x * blockDim.x + threadIdx.x;
    if (id >= N_NODES * F) return;
    int i = id >> LOGF;
    int f = id & (F - 1);
    float di = g_dinv[i];
    float v = agg[id] + m[id] * di * di + b[f];
    agg[id] = fmaxf(v, 0.f);
}

// ---------------- pooling: g[graph] += h2[node], sorted run-length flush ----------------
__global__ void pool_kernel(const float* __restrict__ h2, const int* __restrict__ ngi, int n) {
    int lane = threadIdx.x;              // 32 threads = 32 features
    int start = blockIdx.x * 128;
    if (start >= n) return;
    int end = start + 128; if (end > n) end = n;
    float acc = 0.f;
    int cur = ngi[start];
    for (int i = start; i < end; i++) {
        int gi = ngi[i];
        if (gi != cur) {
            atomicAdd(&g_pool[cur * 32 + lane], acc);
            acc = 0.f; cur = gi;
        }
        acc += h2[i * 32 + lane];
    }
    atomicAdd(&g_pool[cur * 32 + lane], acc);
}

// ---------------- MLP head: relu(g@Wm1+bm1) @ Wm2 + bm2 ----------------
__global__ void mlp_kernel(const float* __restrict__ Wm1, const float* __restrict__ bm1,
                           const float* __restrict__ Wm2, const float* __restrict__ bm2,
                           float* __restrict__ out) {
    __shared__ float gs[32];
    __shared__ float g2s[128];
    int b = blockIdx.x, t = threadIdx.x;
    if (t < 32) gs[t] = g_pool[b * 32 + t];
    __syncthreads();
    float acc = bm1[t];
#pragma unroll
    for (int k = 0; k < 32; k++) acc += gs[k] * Wm1[k * 128 + t];
    g2s[t] = fmaxf(acc, 0.f);
    __syncthreads();
    if (t < 2) {
        float a = bm2[t];
#pragma unroll
        for (int k = 0; k < 128; k++) a += g2s[k] * Wm2[k * 2 + t];
        out[b * 2 + t] = a;
    }
}

// ---------------- host ----------------
extern "C" void kernel_launch(void* const* d_in, const int* in_sizes, int n_in,
                              void* d_out, int out_size) {
    const float* x   = (const float*)d_in[0];
    const int*   ei  = (const int*)d_in[1];
    const float* ew  = (const float*)d_in[2];
    const int*   ngi = (const int*)d_in[3];
    const float* W0  = (const float*)d_in[4];
    const float* b0  = (const float*)d_in[5];
    const float* W1  = (const float*)d_in[6];
    const float* b1  = (const float*)d_in[7];
    const float* Wm1 = (const float*)d_in[8];
    const float* bm1 = (const float*)d_in[9];
    const float* Wm2 = (const float*)d_in[10];
    const float* bm2 = (const float*)d_in[11];
    float* out = (float*)d_out;

    const int* srcp = ei;
    const int* dstp = ei + N_EDGES;

    void *p_deg, *p_h, *p_h2, *p_g, *p_m, *p_m2;
    cudaGetSymbolAddress(&p_deg, g_deg);
    cudaGetSymbolAddress(&p_h,   g_h);
    cudaGetSymbolAddress(&p_h2,  g_h2);
    cudaGetSymbolAddress(&p_g,   g_pool);
    cudaGetSymbolAddress(&p_m,   g_m);
    cudaGetSymbolAddress(&p_m2,  g_m2);

    cudaMemsetAsync(p_deg, 0, N_NODES * sizeof(float));
    cudaMemsetAsync(p_h,   0, N_NODES * 64 * sizeof(float));
    cudaMemsetAsync(p_h2,  0, N_NODES * 32 * sizeof(float));
    cudaMemsetAsync(p_g,   0, N_GRAPHS * 32 * sizeof(float));

    // normalization
    deg_kernel<<<(N_EDGES + 255) / 256, 256>>>(dstp, ew, N_EDGES);
    dinv_kernel<<<(N_NODES + 255) / 256, 256>>>(N_NODES);
    nw_kernel<<<(N_EDGES + 255) / 256, 256>>>(srcp, dstp, ew, N_EDGES);

    // layer 0: 128 -> 64
    gemm_kernel<128, 64><<<(N_NODES + 31) / 32, 256>>>(x, W0, (float*)p_m, N_NODES);
    edge_agg_kernel<5><<<(N_EDGES * 32 + 255) / 256, 256>>>(srcp, dstp, (const float*)p_m, (float*)p_h);
    finalize_kernel<6><<<(N_NODES * 64 + 255) / 256, 256>>>((const float*)p_m, (float*)p_h, b0);

    // layer 1: 64 -> 32
    gemm_kernel<64, 32><<<(N_NODES + 31) / 32, 256>>>((const float*)p_h, W1, (float*)p_m2, N_NODES);
    edge_agg_kernel<4><<<(N_EDGES * 16 + 255) / 256, 256>>>(srcp, dstp, (const float*)p_m2, (float*)p_h2);
    finalize_kernel<5><<<(N_NODES * 32 + 255) / 256, 256>>>((const float*)p_m2, (float*)p_h2, b1);

    // pooling + MLP
    pool_kernel<<<(N_NODES + 127) / 128, 32>>>((const float*)p_h2, ngi, N_NODES);
    mlp_kernel<<<N_GRAPHS, 128>>>(Wm1, bm1, Wm2, bm2, out);
}

// round 3
// speedup vs baseline: 1.4415x; 1.4415x over previous
#include <cuda_runtime.h>
#include <cuda_bf16.h>

#define N_NODES  100000
#define N_EDGES  1600000
#define N_GRAPHS 1000

// ---------------- scratch (static __device__, no allocs) ----------------
__device__ float g_deg[N_NODES];
__device__ float g_dinv[N_NODES];
__device__ float g_nw[N_EDGES];
__device__ float g_m[N_NODES * 64];    // layer0 dense transform
__device__ float g_h[N_NODES * 64];    // layer0 agg -> h (in place)
__device__ float g_m2[N_NODES * 32];   // layer1 dense transform
__device__ float g_h2[N_NODES * 32];   // layer1 agg -> h2 (in place)
__device__ float g_pool[N_GRAPHS * 32];

// ---------------- degree ----------------
__global__ void deg_kernel(const int* __restrict__ dst, const float* __restrict__ w, int E) {
    int e = blockIdx.x * blockDim.x + threadIdx.x;
    if (e < E) atomicAdd(&g_deg[dst[e]], w[e]);
}

__global__ void dinv_kernel(int n) {
    int i = blockIdx.x * blockDim.x + threadIdx.x;
    if (i < n) {
        float d = g_deg[i] + 1.0f;  // self loop weight 1
        g_dinv[i] = rsqrtf(fmaxf(d, 1e-12f));
    }
}

__global__ void nw_kernel(const int* __restrict__ src, const int* __restrict__ dst,
                          const float* __restrict__ w, int E) {
    int e = blockIdx.x * blockDim.x + threadIdx.x;
    if (e < E) g_nw[e] = g_dinv[src[e]] * w[e] * g_dinv[dst[e]];
}

// ---------------- register-blocked GEMM: out[N,M] = X[N,K] @ W[K,M] ----------------
// Tile TR rows x M cols; each thread computes 4 rows x 4 cols.
// FMA/LDS ratio = 8 (per 8-k chunk: 16x LDS.128 vs 128 FFMA).
template <int K, int M, int TR>
__global__ void gemm_kernel(const float* __restrict__ X, const float* __restrict__ W,
                            float* __restrict__ out, int nrows) {
    __shared__ float Ws[K * M];
    __shared__ float Xs[TR * K];
    constexpr int T = TR * M / 16;   // threads per block

    for (int i = threadIdx.x; i < K * M / 4; i += T)
        reinterpret_cast<float4*>(Ws)[i] = reinterpret_cast<const float4*>(W)[i];

    int row0 = blockIdx.x * TR;
    int nr = nrows - row0; if (nr > TR) nr = TR;
    const float4* Xg = reinterpret_cast<const float4*>(X + (size_t)row0 * K);
    for (int i = threadIdx.x; i < nr * K / 4; i += T)
        reinterpret_cast<float4*>(Xs)[i] = Xg[i];
    __syncthreads();

    int tx = threadIdx.x % (M / 4);
    int ty = threadIdx.x / (M / 4);
    int c0 = tx * 4;
    int r0 = ty * 4;

    float4 acc[4];
#pragma unroll
    for (int r = 0; r < 4; r++) acc[r] = make_float4(0.f, 0.f, 0.f, 0.f);

#pragma unroll 2
    for (int kc = 0; kc < K; kc += 8) {
        float4 xa[4][2];
#pragma unroll
        for (int r = 0; r < 4; r++) {
            const float4* xp = reinterpret_cast<const float4*>(&Xs[(r0 + r) * K + kc]);
            xa[r][0] = xp[0];
            xa[r][1] = xp[1];
        }
#pragma unroll
        for (int kk = 0; kk < 8; kk++) {
            float4 w = *reinterpret_cast<const float4*>(&Ws[(kc + kk) * M + c0]);
#pragma unroll
            for (int r = 0; r < 4; r++) {
                float xv = reinterpret_cast<const float*>(&xa[r][kk >> 2])[kk & 3];
                acc[r].x += xv * w.x;
                acc[r].y += xv * w.y;
                acc[r].z += xv * w.z;
                acc[r].w += xv * w.w;
            }
        }
    }

#pragma unroll
    for (int r = 0; r < 4; r++) {
        int row = row0 + r0 + r;
        if (row < nrows)
            *reinterpret_cast<float4*>(&out[(size_t)row * M + c0]) = acc[r];
    }
}

// ---------------- edge aggregation: agg[dst] += m[src] * nw ----------------
// float4 payload per thread, one vector red per thread (4x fewer atomic ops).
// FDIV4 = F/4 threads per edge (16 for F=64, 8 for F=32).
template <int FDIV4>
__global__ void edge_agg_kernel(const int* __restrict__ src, const int* __restrict__ dst,
                                const float* __restrict__ m, float* __restrict__ agg) {
    int id = blockIdx.x * blockDim.x + threadIdx.x;
    int e = id / FDIV4;
    if (e >= N_EDGES) return;
    int f = id % FDIV4;
    int s = src[e];
    int d = dst[e];
    float w = g_nw[e];
    float4 v = reinterpret_cast<const float4*>(m)[(size_t)s * FDIV4 + f];
    float* a = agg + ((size_t)d * FDIV4 + f) * 4;
    asm volatile("red.global.add.v4.f32 [%0], {%1, %2, %3, %4};"
                 :: "l"(a), "f"(v.x * w), "f"(v.y * w), "f"(v.z * w), "f"(v.w * w)
                 : "memory");
}

// ---------------- finalize: h = relu(agg + m*dinv^2 + b), in place on agg ----------------
template <int LOGF>
__global__ void finalize_kernel(const float* __restrict__ m, float* __restrict__ agg,
                                const float* __restrict__ b) {
    const int F = 1 << LOGF;
    int id = blockIdx.x * blockDim.x + threadIdx.x;
    if (id >= N_NODES * F) return;
    int i = id >> LOGF;
    int f = id & (F - 1);
    float di = g_dinv[i];
    float v = agg[id] + m[id] * di * di + b[f];
    agg[id] = fmaxf(v, 0.f);
}

// ---------------- pooling: g[graph] += h2[node], sorted run-length flush ----------------
__global__ void pool_kernel(const float* __restrict__ h2, const int* __restrict__ ngi, int n) {
    int lane = threadIdx.x;              // 32 threads = 32 features
    int start = blockIdx.x * 128;
    if (start >= n) return;
    int end = start + 128; if (end > n) end = n;
    float acc = 0.f;
    int cur = ngi[start];
    for (int i = start; i < end; i++) {
        int gi = ngi[i];
        if (gi != cur) {
            atomicAdd(&g_pool[cur * 32 + lane], acc);
            acc = 0.f; cur = gi;
        }
        acc += h2[i * 32 + lane];
    }
    atomicAdd(&g_pool[cur * 32 + lane], acc);
}

// ---------------- MLP head: relu(g@Wm1+bm1) @ Wm2 + bm2 ----------------
__global__ void mlp_kernel(const float* __restrict__ Wm1, const float* __restrict__ bm1,
                           const float* __restrict__ Wm2, const float* __restrict__ bm2,
                           float* __restrict__ out) {
    __shared__ float gs[32];
    __shared__ float g2s[128];
    int b = blockIdx.x, t = threadIdx.x;
    if (t < 32) gs[t] = g_pool[b * 32 + t];
    __syncthreads();
    float acc = bm1[t];
#pragma unroll
    for (int k = 0; k < 32; k++) acc += gs[k] * Wm1[k * 128 + t];
    g2s[t] = fmaxf(acc, 0.f);
    __syncthreads();
    if (t < 2) {
        float a = bm2[t];
#pragma unroll
        for (int k = 0; k < 128; k++) a += g2s[k] * Wm2[k * 2 + t];
        out[b * 2 + t] = a;
    }
}

// ---------------- host ----------------
extern "C" void kernel_launch(void* const* d_in, const int* in_sizes, int n_in,
                              void* d_out, int out_size) {
    const float* x   = (const float*)d_in[0];
    const int*   ei  = (const int*)d_in[1];
    const float* ew  = (const float*)d_in[2];
    const int*   ngi = (const int*)d_in[3];
    const float* W0  = (const float*)d_in[4];
    const float* b0  = (const float*)d_in[5];
    const float* W1  = (const float*)d_in[6];
    const float* b1  = (const float*)d_in[7];
    const float* Wm1 = (const float*)d_in[8];
    const float* bm1 = (const float*)d_in[9];
    const float* Wm2 = (const float*)d_in[10];
    const float* bm2 = (const float*)d_in[11];
    float* out = (float*)d_out;

    const int* srcp = ei;
    const int* dstp = ei + N_EDGES;

    void *p_deg, *p_h, *p_h2, *p_g, *p_m, *p_m2;
    cudaGetSymbolAddress(&p_deg, g_deg);
    cudaGetSymbolAddress(&p_h,   g_h);
    cudaGetSymbolAddress(&p_h2,  g_h2);
    cudaGetSymbolAddress(&p_g,   g_pool);
    cudaGetSymbolAddress(&p_m,   g_m);
    cudaGetSymbolAddress(&p_m2,  g_m2);

    cudaMemsetAsync(p_deg, 0, N_NODES * sizeof(float));
    cudaMemsetAsync(p_h,   0, N_NODES * 64 * sizeof(float));
    cudaMemsetAsync(p_h2,  0, N_NODES * 32 * sizeof(float));
    cudaMemsetAsync(p_g,   0, N_GRAPHS * 32 * sizeof(float));

    // normalization
    deg_kernel<<<(N_EDGES + 255) / 256, 256>>>(dstp, ew, N_EDGES);
    dinv_kernel<<<(N_NODES + 255) / 256, 256>>>(N_NODES);
    nw_kernel<<<(N_EDGES + 255) / 256, 256>>>(srcp, dstp, ew, N_EDGES);

    // layer 0: 128 -> 64   (tile 32 rows x 64 cols, 128 threads, 48KB smem)
    gemm_kernel<128, 64, 32><<<(N_NODES + 31) / 32, 128>>>(x, W0, (float*)p_m, N_NODES);
    edge_agg_kernel<16><<<(N_EDGES * 16 + 255) / 256, 256>>>(srcp, dstp, (const float*)p_m, (float*)p_h);
    finalize_kernel<6><<<(N_NODES * 64 + 255) / 256, 256>>>((const float*)p_m, (float*)p_h, b0);

    // layer 1: 64 -> 32    (tile 64 rows x 32 cols, 128 threads, 24KB smem)
    gemm_kernel<64, 32, 64><<<(N_NODES + 63) / 64, 128>>>((const float*)p_h, W1, (float*)p_m2, N_NODES);
    edge_agg_kernel<8><<<(N_EDGES * 8 + 255) / 256, 256>>>(srcp, dstp, (const float*)p_m2, (float*)p_h2);
    finalize_kernel<5><<<(N_NODES * 32 + 255) / 256, 256>>>((const float*)p_m2, (float*)p_h2, b1);

    // pooling + MLP
    pool_kernel<<<(N_NODES + 127) / 128, 32>>>((const float*)p_h2, ngi, N_NODES);
    mlp_kernel<<<N_GRAPHS, 128>>>(Wm1, bm1, Wm2, bm2, out);
}